// round 13
// baseline (speedup 1.0000x reference)
#include <cuda_runtime.h>

#define NSRC 20000
#define NTAR 20000
#define NTOT (NSRC + NTAR)
#define NBIN 2048
#define ZMINV (-4.0f)
#define BINW (8.0f / NBIN)
#define INVBINW (NBIN / 8.0f)
#define NS   16
#define SLABQ (NSRC / NS)                  // 1250
#define NB1  40
#define NT1  1024
#define GRID3 296
#define NT3  256
#define TILE 128
#define TPG  1024                          // targets per group
#define NGRP 20
#define NBLK4 148
#define NT4  512
#define TILEF 256
#define NSTF ((NSRC + TILEF - 1) / TILEF)  // 79
#define FLT_BIG 3.402823466e38f
#define INF_KEY 0x7F800000

// ---- device-global scratch (no allocation allowed) ----
__device__ int    g_histS[NBIN];
__device__ int    g_histT[NBIN];
__device__ int    g_lut[NBIN];
__device__ int    g_fill[2 * NS];
__device__ float  g_s8[NSRC * 8];         // slab-sorted packed {x,x,y,y,z,z,w,w}
__device__ float4 g_t4[NTAR];             // slab-sorted targets {x,y,z,||t||^2}
__device__ int    g_pmk[NTAR];            // per-sorted-target min key
__device__ int    g_gw[NGRP][2];          // window src range
__device__ float  g_gz[NGRP][2];          // window z-edges
__device__ int    g_upref[NGRP + 1];
// extended-window info (window widened by 1 slab each side)
__device__ int    g_eL0[NGRP], g_eL1[NGRP];   // extra src range, left
__device__ int    g_eR0[NGRP], g_eR1[NGRP];   // extra src range, right
__device__ float  g_em0[NGRP], g_em1[NGRP];   // extended z-edges
__device__ int    g_fcnt[NGRP];               // failures per group
__device__ int    g_flistg[NGRP * TPG];       // per-group failure lists
__device__ int    g_nfail;                    // residual failures (flat)
__device__ int    g_flist[NTAR];
__device__ unsigned g_tick1, g_tick4;         // last-block tickets
__device__ unsigned          g_bar_cnt;
__device__ volatile unsigned g_bar_gen;       // monotonic

union F2U { unsigned long long u; float2 f; };
__device__ __forceinline__ unsigned long long pk(float lo, float hi) {
    F2U t; t.f = make_float2(lo, hi); return t.u;
}
__device__ __forceinline__ F2U fma2(unsigned long long a, unsigned long long b,
                                    unsigned long long c) {
    F2U d;
    asm("fma.rn.f32x2 %0, %1, %2, %3;" : "=l"(d.u) : "l"(a), "l"(b), "l"(c));
    return d;
}
__device__ __forceinline__ int fkey(float f) {
    int b = __float_as_int(f);
    return b >= 0 ? b : (b ^ 0x7FFFFFFF);
}
__device__ __forceinline__ float fdec(int k) {
    return __int_as_float(k >= 0 ? k : (k ^ 0x7FFFFFFF));
}
__device__ __forceinline__ int finebin(float z) {
    int b = (int)floorf((z - ZMINV) * INVBINW);
    return min(max(b, 0), NBIN - 1);
}

__device__ __forceinline__ void gbar(int nblk) {
    __threadfence();
    __syncthreads();
    if (threadIdx.x == 0) {
        unsigned gen = g_bar_gen;
        if (atomicAdd(&g_bar_cnt, 1u) == (unsigned)nblk - 1) {
            g_bar_cnt = 0;
            __threadfence();
            g_bar_gen = gen + 1;
        } else {
            while (g_bar_gen == gen) __nanosleep(32);
            __threadfence();
        }
    }
    __syncthreads();
}

// inclusive scan of 2048 bins with 1024 threads (2 bins each)
__device__ void scan2048_1024(const int* hist, int* s_cum, int* s_ws) {
    int tid = threadIdx.x;
    int base = tid * 2;
    int2 q = *(const int2*)&hist[base];
    int tot = q.x + q.y;
    int lane = tid & 31, wid = tid >> 5;
    int inc = tot;
    #pragma unroll
    for (int o = 1; o < 32; o <<= 1) {
        int y = __shfl_up_sync(0xffffffffu, inc, o);
        if (lane >= o) inc += y;
    }
    if (lane == 31) s_ws[wid] = inc;
    __syncthreads();
    if (wid == 0) {
        int w = s_ws[lane];
        #pragma unroll
        for (int o = 1; o < 32; o <<= 1) {
            int y = __shfl_up_sync(0xffffffffu, w, o);
            if (lane >= o) w += y;
        }
        s_ws[lane] = w;
    }
    __syncthreads();
    int run = inc - tot + (wid ? s_ws[wid - 1] : 0);
    run += q.x; s_cum[base]     = run;
    run += q.y; s_cum[base + 1] = run;
    __syncthreads();
}

// ---- K1: reset + histograms; last (ticketed) block does all setup ----
__global__ __launch_bounds__(NT1) void hist_setup_kernel(const float* __restrict__ src,
                                                         const float* __restrict__ tar) {
    __shared__ int   s_cum[NBIN];
    __shared__ int   s_ws[32];
    __shared__ int   s_bnd[NS + 1];
    __shared__ int   s_soff[NS + 1];
    __shared__ int   s_toff[NS + 1];
    __shared__ float s_edge[NS + 1];
    __shared__ int   s_last;
    int tid = threadIdx.x;
    int i = blockIdx.x * NT1 + tid;

    if (i == 0) g_nfail = 0;
    if (i < NGRP) g_fcnt[i] = 0;
    if (i < NTAR) g_pmk[i] = INF_KEY;
    if (i < NTOT) {
        if (i < NSRC) atomicAdd(&g_histS[finebin(src[3 * i + 2])], 1);
        else          atomicAdd(&g_histT[finebin(tar[3 * (i - NSRC) + 2])], 1);
    }
    __threadfence();
    __syncthreads();
    if (tid == 0) {
        unsigned t = atomicAdd(&g_tick1, 1u);
        s_last = (t == NB1 - 1) ? 1 : 0;
        if (s_last) g_tick1 = 0;
    }
    __syncthreads();
    if (!s_last) return;
    __threadfence();

    // --- setup (one block) ---
    scan2048_1024(g_histS, s_cum, s_ws);
    if (tid >= 1 && tid < NS) {
        int tgt = tid * SLABQ;
        int lo = 0, hi = NBIN - 1;
        while (lo < hi) { int mid = (lo + hi) >> 1; if (s_cum[mid] >= tgt) hi = mid; else lo = mid + 1; }
        s_bnd[tid] = lo + 1;
    }
    if (tid == 0) { s_bnd[0] = 0; s_bnd[NS] = NBIN; }
    __syncthreads();
    if (tid <= NS) {
        s_soff[tid] = (tid == 0) ? 0 : s_cum[s_bnd[tid] - 1];
        s_edge[tid] = (tid == 0) ? -1e30f :
                      (tid == NS) ? 1e30f : (ZMINV + (float)s_bnd[tid] * BINW);
    }
    __syncthreads();
    for (int b = tid; b < NBIN; b += NT1) {
        int s = 0;
        #pragma unroll
        for (int k = 1; k < NS; k++) s += (s_bnd[k] <= b) ? 1 : 0;
        g_lut[b] = s;
        g_histS[b] = 0;
    }
    __syncthreads();
    scan2048_1024(g_histT, s_cum, s_ws);
    if (tid <= NS) s_toff[tid] = (tid == 0) ? 0 : s_cum[s_bnd[tid] - 1];
    for (int b = tid; b < NBIN; b += NT1) g_histT[b] = 0;
    __syncthreads();
    if (tid < NS) {
        g_fill[tid]      = s_soff[tid];
        g_fill[NS + tid] = s_toff[tid];
    }
    if (tid < NGRP) {
        int j0 = tid * TPG;
        int j1 = min(j0 + TPG, NTAR) - 1;
        int sf = 0, sl = 0;
        #pragma unroll
        for (int k = 1; k < NS; k++) {
            sf += (s_toff[k] <= j0) ? 1 : 0;
            sl += (s_toff[k] <= j1) ? 1 : 0;
        }
        int lo = max(sf - 1, 0), hi = min(sl + 1, NS - 1);
        g_gw[tid][0] = s_soff[lo];
        g_gw[tid][1] = s_soff[hi + 1];
        g_gz[tid][0] = s_edge[lo];
        g_gz[tid][1] = s_edge[hi + 1];
        // extended window (+1 slab each side) for the bounded fallback
        int lo2 = max(lo - 1, 0), hi2 = min(hi + 1, NS - 1);
        g_eL0[tid] = s_soff[lo2];  g_eL1[tid] = s_soff[lo];
        g_eR0[tid] = s_soff[hi + 1]; g_eR1[tid] = s_soff[hi2 + 1];
        g_em0[tid] = s_edge[lo2];  g_em1[tid] = s_edge[hi2 + 1];
    }
    __syncthreads();
    if (tid == 0) {
        int run = 0;
        for (int g = 0; g < NGRP; g++) {
            g_upref[g] = run;
            run += (g_gw[g][1] - g_gw[g][0] + TILE - 1) / TILE;
        }
        g_upref[NGRP] = run;
    }
}

// ---- K2: block-aggregated counting-sort scatter ----
__global__ __launch_bounds__(NT1) void scatter_kernel(const float* __restrict__ src,
                                                      const float* __restrict__ tar) {
    __shared__ int s_hcnt[2 * NS];
    __shared__ int s_hbase[2 * NS];
    int tid = threadIdx.x;
    int i = blockIdx.x * NT1 + tid;
    bool valid = (i < NTOT);
    int slab = 0;
    float x = 0.f, y = 0.f, z = 0.f;
    if (valid) {
        if (i < NSRC) {
            x = src[3 * i]; y = src[3 * i + 1]; z = src[3 * i + 2];
            slab = g_lut[finebin(z)];
        } else {
            int t = i - NSRC;
            x = tar[3 * t]; y = tar[3 * t + 1]; z = tar[3 * t + 2];
            slab = NS + g_lut[finebin(z)];
        }
    }
    if (tid < 2 * NS) s_hcnt[tid] = 0;
    __syncthreads();
    int lpos = 0;
    if (valid) lpos = atomicAdd(&s_hcnt[slab], 1);
    __syncthreads();
    if (tid < 2 * NS && s_hcnt[tid] > 0)
        s_hbase[tid] = atomicAdd(&g_fill[tid], s_hcnt[tid]);
    __syncthreads();
    if (valid) {
        int pos = s_hbase[slab] + lpos;
        float w = x * x + y * y + z * z;
        if (i < NSRC) {
            float4* p = (float4*)g_s8;
            p[2 * pos]     = make_float4(x, x, y, y);
            p[2 * pos + 1] = make_float4(z, z, w, w);
        } else {
            g_t4[pos] = make_float4(x, y, z, w);
        }
    }
}

// ---- K3: windowed pairwise min, 4 targets/lane ----
__global__ __launch_bounds__(NT3) void pair_kernel() {
    __shared__ float4 s_tile[2 * TILE];
    __shared__ int    s_up[NGRP + 1];
    int tid = threadIdx.x;
    if (tid <= NGRP) s_up[tid] = g_upref[tid];
    __syncthreads();
    int U = s_up[NGRP];
    for (int u = blockIdx.x; u < U; u += GRID3) {
        int g = 0;
        while (u >= s_up[g + 1]) g++;
        int ti = u - s_up[g];
        int s0 = g_gw[g][0] + ti * TILE;
        int cnt = min(TILE, g_gw[g][1] - s0);

        int tb = g * TPG + tid;
        float c[4][3];
        #pragma unroll
        for (int k = 0; k < 4; k++) {
            int t = tb + k * NT3;
            if (t < NTAR) {
                float4 q = g_t4[t];
                c[k][0] = -2.f * q.x; c[k][1] = -2.f * q.y; c[k][2] = -2.f * q.z;
            } else {
                c[k][0] = c[k][1] = c[k][2] = 0.f;
            }
        }
        unsigned long long txp0 = pk(c[0][0], c[1][0]), txp1 = pk(c[2][0], c[3][0]);
        unsigned long long typ0 = pk(c[0][1], c[1][1]), typ1 = pk(c[2][1], c[3][1]);
        unsigned long long tzp0 = pk(c[0][2], c[1][2]), tzp1 = pk(c[2][2], c[3][2]);

        __syncthreads();
        if (tid < 2 * cnt) s_tile[tid] = ((const float4*)g_s8)[2 * s0 + tid];
        __syncthreads();

        float m0 = FLT_BIG, m1 = FLT_BIG, m2 = FLT_BIG, m3 = FLT_BIG;
        const ulonglong2* st = (const ulonglong2*)s_tile;
        #pragma unroll 4
        for (int j = 0; j < cnt; j++) {
            ulonglong2 q = st[2 * j];
            ulonglong2 r = st[2 * j + 1];
            F2U v0 = fma2(q.x, txp0, r.y);
            F2U v1 = fma2(q.x, txp1, r.y);
            v0 = fma2(q.y, typ0, v0.u);
            v1 = fma2(q.y, typ1, v1.u);
            v0 = fma2(r.x, tzp0, v0.u);
            v1 = fma2(r.x, tzp1, v1.u);
            m0 = fminf(m0, v0.f.x);
            m1 = fminf(m1, v0.f.y);
            m2 = fminf(m2, v1.f.x);
            m3 = fminf(m3, v1.f.y);
        }
        if (tb < NTAR)           atomicMin(&g_pmk[tb],           fkey(m0));
        if (tb + NT3 < NTAR)     atomicMin(&g_pmk[tb + NT3],     fkey(m1));
        if (tb + 2 * NT3 < NTAR) atomicMin(&g_pmk[tb + 2 * NT3], fkey(m2));
        if (tb + 3 * NT3 < NTAR) atomicMin(&g_pmk[tb + 3 * NT3], fkey(m3));
    }
}

// ---- K4: margin -> per-group lists -> bounded fallback -> residual -> sum ----
__global__ __launch_bounds__(NT4) void finish_kernel(float* __restrict__ out) {
    __shared__ float4 s_tile[2 * TILEF];
    __shared__ float  s_fred[16];
    __shared__ int    s_up2[NGRP + 1];
    __shared__ int    s_last;
    int tid = threadIdx.x;
    int gid = blockIdx.x * NT4 + tid;

    // A: margin check vs original window -> per-group failure lists
    if (gid < NTAR) {
        int g = gid >> 10;                      // TPG == 1024
        float4 t = g_t4[gid];
        float d2 = fdec(g_pmk[gid]) + t.w;
        float mm = fminf(t.z - g_gz[g][0], g_gz[g][1] - t.z);
        if (!(d2 <= mm * mm)) {
            int slot = atomicAdd(&g_fcnt[g], 1);
            g_flistg[g * TPG + slot] = gid;
        }
    }
    gbar(NBLK4);

    // B: scan ONLY the +1-slab extension ranges, per group, 2 targets/lane
    if (tid == 0) {
        int run = 0;
        #pragma unroll
        for (int g = 0; g < NGRP; g++) {
            int sz = (g_eL1[g] - g_eL0[g]) + (g_eR1[g] - g_eR0[g]);
            int t = (g_fcnt[g] > 0 && sz > 0) ? (sz + TILEF - 1) / TILEF : 0;
            s_up2[g] = run;
            run += t;
        }
        s_up2[NGRP] = run;
    }
    __syncthreads();
    int U2 = s_up2[NGRP];
    for (int u = blockIdx.x; u < U2; u += NBLK4) {
        int g = 0;
        while (u >= s_up2[g + 1]) g++;
        int ti = u - s_up2[g];
        int L0 = g_eL0[g], Lsz = g_eL1[g] - L0;
        int R0 = g_eR0[g], Rsz = g_eR1[g] - R0;
        int cbase = ti * TILEF;
        int cnt = min(TILEF, Lsz + Rsz - cbase);

        int fc = g_fcnt[g];
        int j0 = (tid < fc)       ? g_flistg[g * TPG + tid]       : -1;
        int j1 = (tid + NT4 < fc) ? g_flistg[g * TPG + tid + NT4] : -1;
        float ax = 0.f, ay = 0.f, az = 0.f, bx = 0.f, by = 0.f, bz = 0.f;
        if (j0 >= 0) { float4 t = g_t4[j0]; ax = -2.f * t.x; ay = -2.f * t.y; az = -2.f * t.z; }
        if (j1 >= 0) { float4 t = g_t4[j1]; bx = -2.f * t.x; by = -2.f * t.y; bz = -2.f * t.z; }
        unsigned long long txp = pk(ax, bx), typ = pk(ay, by), tzp = pk(az, bz);

        __syncthreads();
        if (tid < 2 * cnt) {
            int e = cbase + (tid >> 1);
            int si = (e < Lsz) ? (L0 + e) : (R0 + e - Lsz);
            s_tile[tid] = ((const float4*)g_s8)[2 * si + (tid & 1)];
        }
        __syncthreads();

        float m0 = FLT_BIG, m1 = FLT_BIG;
        const ulonglong2* st = (const ulonglong2*)s_tile;
        #pragma unroll 4
        for (int j = 0; j < cnt; j++) {
            ulonglong2 q = st[2 * j];
            ulonglong2 r = st[2 * j + 1];
            F2U v = fma2(q.x, txp, r.y);
            v = fma2(q.y, typ, v.u);
            v = fma2(r.x, tzp, v.u);
            m0 = fminf(m0, v.f.x);
            m1 = fminf(m1, v.f.y);
        }
        if (j0 >= 0) atomicMin(&g_pmk[j0], fkey(m0));
        if (j1 >= 0) atomicMin(&g_pmk[j1], fkey(m1));
    }
    gbar(NBLK4);

    // C: re-check vs EXTENDED edges; survivors -> flat residual list
    {
        int g = gid / TPG, idx = gid % TPG;     // covers NGRP*TPG = 20480 slots
        if (g < NGRP && idx < g_fcnt[g]) {
            int j = g_flistg[g * TPG + idx];
            float4 t = g_t4[j];
            float d2 = fdec(g_pmk[j]) + t.w;
            float mm = fminf(t.z - g_em0[g], g_em1[g] - t.z);
            if (!(d2 <= mm * mm))
                g_flist[atomicAdd(&g_nfail, 1)] = j;
        }
    }
    gbar(NBLK4);

    // D: full brute force for the (few) residual targets, 4/lane
    int nf = g_nfail;
    if (nf > 0) {
        int nquad = (nf + 3) / 4;
        int fgroups = (nquad + NT4 - 1) / NT4;
        int UD = fgroups * NSTF;
        for (int u = blockIdx.x; u < UD; u += NBLK4) {
            int fg = u / NSTF, ti = u % NSTF;
            int base = 4 * (fg * NT4 + tid);
            int jj[4];
            float c[4][3];
            #pragma unroll
            for (int k = 0; k < 4; k++) {
                jj[k] = (base + k < nf) ? g_flist[base + k] : -1;
                if (jj[k] >= 0) {
                    float4 t = g_t4[jj[k]];
                    c[k][0] = -2.f * t.x; c[k][1] = -2.f * t.y; c[k][2] = -2.f * t.z;
                } else {
                    c[k][0] = c[k][1] = c[k][2] = 0.f;
                }
            }
            unsigned long long txp0 = pk(c[0][0], c[1][0]), txp1 = pk(c[2][0], c[3][0]);
            unsigned long long typ0 = pk(c[0][1], c[1][1]), typ1 = pk(c[2][1], c[3][1]);
            unsigned long long tzp0 = pk(c[0][2], c[1][2]), tzp1 = pk(c[2][2], c[3][2]);

            int s0 = ti * TILEF;
            int cnt = min(TILEF, NSRC - s0);
            __syncthreads();
            if (tid < 2 * cnt) s_tile[tid] = ((const float4*)g_s8)[2 * s0 + tid];
            __syncthreads();

            float m0 = FLT_BIG, m1 = FLT_BIG, m2 = FLT_BIG, m3 = FLT_BIG;
            const ulonglong2* st = (const ulonglong2*)s_tile;
            #pragma unroll 4
            for (int j = 0; j < cnt; j++) {
                ulonglong2 q = st[2 * j];
                ulonglong2 r = st[2 * j + 1];
                F2U v0 = fma2(q.x, txp0, r.y);
                F2U v1 = fma2(q.x, txp1, r.y);
                v0 = fma2(q.y, typ0, v0.u);
                v1 = fma2(q.y, typ1, v1.u);
                v0 = fma2(r.x, tzp0, v0.u);
                v1 = fma2(r.x, tzp1, v1.u);
                m0 = fminf(m0, v0.f.x);
                m1 = fminf(m1, v0.f.y);
                m2 = fminf(m2, v1.f.x);
                m3 = fminf(m3, v1.f.y);
            }
            if (jj[0] >= 0) atomicMin(&g_pmk[jj[0]], fkey(m0));
            if (jj[1] >= 0) atomicMin(&g_pmk[jj[1]], fkey(m1));
            if (jj[2] >= 0) atomicMin(&g_pmk[jj[2]], fkey(m2));
            if (jj[3] >= 0) atomicMin(&g_pmk[jj[3]], fkey(m3));
        }
    }

    // Ticket: last block does the fixed-order final sum
    __threadfence();
    __syncthreads();
    if (tid == 0) {
        unsigned t = atomicAdd(&g_tick4, 1u);
        s_last = (t == NBLK4 - 1) ? 1 : 0;
        if (s_last) g_tick4 = 0;
    }
    __syncthreads();
    if (!s_last) return;
    __threadfence();

    float acc = 0.f;
    for (int j = tid; j < NTAR; j += NT4)
        acc += fdec(g_pmk[j]) + g_t4[j].w;
    int lane = tid & 31, wid = tid >> 5;
    #pragma unroll
    for (int o = 16; o; o >>= 1) acc += __shfl_down_sync(0xffffffffu, acc, o);
    if (lane == 0) s_fred[wid] = acc;
    __syncthreads();
    if (wid == 0) {
        float v = (lane < 16) ? s_fred[lane] : 0.f;
        #pragma unroll
        for (int o = 8; o; o >>= 1) v += __shfl_down_sync(0xffffffffu, v, o);
        if (lane == 0) out[0] = 0.5f * v;
    }
}

extern "C" void kernel_launch(void* const* d_in, const int* in_sizes, int n_in,
                              void* d_out, int out_size) {
    const float* src = (const float*)d_in[0];   // [20000, 3] fp32
    const float* tar = (const float*)d_in[1];   // [20000, 3] fp32
    float* out = (float*)d_out;                 // scalar fp32

    hist_setup_kernel<<<NB1, NT1>>>(src, tar);
    scatter_kernel<<<NB1, NT1>>>(src, tar);
    pair_kernel<<<GRID3, NT3>>>();
    finish_kernel<<<NBLK4, NT4>>>(out);
}

// round 16
// speedup vs baseline: 1.1452x; 1.1452x over previous
#include <cuda_runtime.h>

#define NSRC 20000
#define NTAR 20000
#define NTOT (NSRC + NTAR)
#define NBIN 2048
#define ZMINV (-4.0f)
#define BINW (8.0f / NBIN)
#define INVBINW (NBIN / 8.0f)
#define NS   16
#define SLABQ (NSRC / NS)                  // 1250
#define NB1  40
#define NT1  1024
#define GRID3 296
#define NT3  256
#define TILE 128
#define TPG  1024                          // targets per group
#define NGRP 20
#define NBLK4 148
#define NT4  512
#define TILEF 256
#define NSTF ((NSRC + TILEF - 1) / TILEF)  // 79
#define FLT_BIG 3.402823466e38f
#define INF_KEY 0x7F800000

// ---- device-global scratch (no allocation allowed) ----
__device__ int    g_histS[NBIN];
__device__ int    g_histT[NBIN];
__device__ int    g_lut[NBIN];
__device__ int    g_fill[2 * NS];
__device__ float  g_s8[NSRC * 8];         // slab-sorted packed {x,x,y,y,z,z,w,w}
__device__ float4 g_t4[NTAR];             // slab-sorted targets {x,y,z,||t||^2}
__device__ int    g_pmk[NTAR];            // per-sorted-target min key
__device__ int    g_gw[NGRP][2];          // window src range
__device__ float  g_gz[NGRP][2];          // window z-edges
__device__ int    g_upref[NGRP + 1];
// extended-window info (window widened by 1 slab each side)
__device__ int    g_eL0[NGRP], g_eL1[NGRP];
__device__ int    g_eR0[NGRP], g_eR1[NGRP];
__device__ float  g_em0[NGRP], g_em1[NGRP];
__device__ int    g_fcnt[NGRP];
__device__ int    g_flistg[NGRP * TPG];
__device__ int    g_nfail;
__device__ int    g_flist[NTAR];
__device__ unsigned g_tick1, g_tick4;
__device__ unsigned          g_bar_cnt;
__device__ volatile unsigned g_bar_gen;

union F2U { unsigned long long u; float2 f; };
__device__ __forceinline__ unsigned long long pk(float lo, float hi) {
    F2U t; t.f = make_float2(lo, hi); return t.u;
}
__device__ __forceinline__ F2U fma2(unsigned long long a, unsigned long long b,
                                    unsigned long long c) {
    F2U d;
    asm("fma.rn.f32x2 %0, %1, %2, %3;" : "=l"(d.u) : "l"(a), "l"(b), "l"(c));
    return d;
}
__device__ __forceinline__ int fkey(float f) {
    int b = __float_as_int(f);
    return b >= 0 ? b : (b ^ 0x7FFFFFFF);
}
__device__ __forceinline__ float fdec(int k) {
    return __int_as_float(k >= 0 ? k : (k ^ 0x7FFFFFFF));
}
__device__ __forceinline__ int finebin(float z) {
    int b = (int)floorf((z - ZMINV) * INVBINW);
    return min(max(b, 0), NBIN - 1);
}

__device__ __forceinline__ void gbar(int nblk) {
    __threadfence();
    __syncthreads();
    if (threadIdx.x == 0) {
        unsigned gen = g_bar_gen;
        if (atomicAdd(&g_bar_cnt, 1u) == (unsigned)nblk - 1) {
            g_bar_cnt = 0;
            __threadfence();
            g_bar_gen = gen + 1;
        } else {
            while (g_bar_gen == gen) __nanosleep(32);
            __threadfence();
        }
    }
    __syncthreads();
}

// inclusive scan of 2048 bins with 1024 threads (2 bins each)
__device__ void scan2048_1024(const int* hist, int* s_cum, int* s_ws) {
    int tid = threadIdx.x;
    int base = tid * 2;
    int2 q = *(const int2*)&hist[base];
    int tot = q.x + q.y;
    int lane = tid & 31, wid = tid >> 5;
    int inc = tot;
    #pragma unroll
    for (int o = 1; o < 32; o <<= 1) {
        int y = __shfl_up_sync(0xffffffffu, inc, o);
        if (lane >= o) inc += y;
    }
    if (lane == 31) s_ws[wid] = inc;
    __syncthreads();
    if (wid == 0) {
        int w = s_ws[lane];
        #pragma unroll
        for (int o = 1; o < 32; o <<= 1) {
            int y = __shfl_up_sync(0xffffffffu, w, o);
            if (lane >= o) w += y;
        }
        s_ws[lane] = w;
    }
    __syncthreads();
    int run = inc - tot + (wid ? s_ws[wid - 1] : 0);
    run += q.x; s_cum[base]     = run;
    run += q.y; s_cum[base + 1] = run;
    __syncthreads();
}

// ---- K1: reset + histograms; last (ticketed) block does all setup ----
__global__ __launch_bounds__(NT1) void hist_setup_kernel(const float* __restrict__ src,
                                                         const float* __restrict__ tar) {
    __shared__ int   s_cum[NBIN];
    __shared__ int   s_ws[32];
    __shared__ int   s_bnd[NS + 1];
    __shared__ int   s_soff[NS + 1];
    __shared__ int   s_toff[NS + 1];
    __shared__ float s_edge[NS + 1];
    __shared__ int   s_last;
    int tid = threadIdx.x;
    int i = blockIdx.x * NT1 + tid;

    if (i == 0) g_nfail = 0;
    if (i < NGRP) g_fcnt[i] = 0;
    if (i < NTAR) g_pmk[i] = INF_KEY;
    if (i < NTOT) {
        if (i < NSRC) atomicAdd(&g_histS[finebin(src[3 * i + 2])], 1);
        else          atomicAdd(&g_histT[finebin(tar[3 * (i - NSRC) + 2])], 1);
    }
    __threadfence();
    __syncthreads();
    if (tid == 0) {
        unsigned t = atomicAdd(&g_tick1, 1u);
        s_last = (t == NB1 - 1) ? 1 : 0;
        if (s_last) g_tick1 = 0;
    }
    __syncthreads();
    if (!s_last) return;
    __threadfence();

    scan2048_1024(g_histS, s_cum, s_ws);
    if (tid >= 1 && tid < NS) {
        int tgt = tid * SLABQ;
        int lo = 0, hi = NBIN - 1;
        while (lo < hi) { int mid = (lo + hi) >> 1; if (s_cum[mid] >= tgt) hi = mid; else lo = mid + 1; }
        s_bnd[tid] = lo + 1;
    }
    if (tid == 0) { s_bnd[0] = 0; s_bnd[NS] = NBIN; }
    __syncthreads();
    if (tid <= NS) {
        s_soff[tid] = (tid == 0) ? 0 : s_cum[s_bnd[tid] - 1];
        s_edge[tid] = (tid == 0) ? -1e30f :
                      (tid == NS) ? 1e30f : (ZMINV + (float)s_bnd[tid] * BINW);
    }
    __syncthreads();
    for (int b = tid; b < NBIN; b += NT1) {
        int s = 0;
        #pragma unroll
        for (int k = 1; k < NS; k++) s += (s_bnd[k] <= b) ? 1 : 0;
        g_lut[b] = s;
        g_histS[b] = 0;
    }
    __syncthreads();
    scan2048_1024(g_histT, s_cum, s_ws);
    if (tid <= NS) s_toff[tid] = (tid == 0) ? 0 : s_cum[s_bnd[tid] - 1];
    for (int b = tid; b < NBIN; b += NT1) g_histT[b] = 0;
    __syncthreads();
    if (tid < NS) {
        g_fill[tid]      = s_soff[tid];
        g_fill[NS + tid] = s_toff[tid];
    }
    if (tid < NGRP) {
        int j0 = tid * TPG;
        int j1 = min(j0 + TPG, NTAR) - 1;
        int sf = 0, sl = 0;
        #pragma unroll
        for (int k = 1; k < NS; k++) {
            sf += (s_toff[k] <= j0) ? 1 : 0;
            sl += (s_toff[k] <= j1) ? 1 : 0;
        }
        int lo = max(sf - 1, 0), hi = min(sl + 1, NS - 1);
        g_gw[tid][0] = s_soff[lo];
        g_gw[tid][1] = s_soff[hi + 1];
        g_gz[tid][0] = s_edge[lo];
        g_gz[tid][1] = s_edge[hi + 1];
        int lo2 = max(lo - 1, 0), hi2 = min(hi + 1, NS - 1);
        g_eL0[tid] = s_soff[lo2];   g_eL1[tid] = s_soff[lo];
        g_eR0[tid] = s_soff[hi + 1]; g_eR1[tid] = s_soff[hi2 + 1];
        g_em0[tid] = s_edge[lo2];   g_em1[tid] = s_edge[hi2 + 1];
    }
    __syncthreads();
    if (tid == 0) {
        int run = 0;
        for (int g = 0; g < NGRP; g++) {
            g_upref[g] = run;
            run += (g_gw[g][1] - g_gw[g][0] + TILE - 1) / TILE;
        }
        g_upref[NGRP] = run;
    }
}

// ---- K2: block-aggregated counting-sort scatter ----
__global__ __launch_bounds__(NT1) void scatter_kernel(const float* __restrict__ src,
                                                      const float* __restrict__ tar) {
    __shared__ int s_hcnt[2 * NS];
    __shared__ int s_hbase[2 * NS];
    int tid = threadIdx.x;
    int i = blockIdx.x * NT1 + tid;
    bool valid = (i < NTOT);
    int slab = 0;
    float x = 0.f, y = 0.f, z = 0.f;
    if (valid) {
        if (i < NSRC) {
            x = src[3 * i]; y = src[3 * i + 1]; z = src[3 * i + 2];
            slab = g_lut[finebin(z)];
        } else {
            int t = i - NSRC;
            x = tar[3 * t]; y = tar[3 * t + 1]; z = tar[3 * t + 2];
            slab = NS + g_lut[finebin(z)];
        }
    }
    if (tid < 2 * NS) s_hcnt[tid] = 0;
    __syncthreads();
    int lpos = 0;
    if (valid) lpos = atomicAdd(&s_hcnt[slab], 1);
    __syncthreads();
    if (tid < 2 * NS && s_hcnt[tid] > 0)
        s_hbase[tid] = atomicAdd(&g_fill[tid], s_hcnt[tid]);
    __syncthreads();
    if (valid) {
        int pos = s_hbase[slab] + lpos;
        float w = x * x + y * y + z * z;
        if (i < NSRC) {
            float4* p = (float4*)g_s8;
            p[2 * pos]     = make_float4(x, x, y, y);
            p[2 * pos + 1] = make_float4(z, z, w, w);
        } else {
            g_t4[pos] = make_float4(x, y, z, w);
        }
    }
}

// ---- K3: windowed pairwise min, 4 targets/lane ----
__global__ __launch_bounds__(NT3) void pair_kernel() {
    __shared__ float4 s_tile[2 * TILE];
    __shared__ int    s_up[NGRP + 1];
    int tid = threadIdx.x;
    if (tid <= NGRP) s_up[tid] = g_upref[tid];
    __syncthreads();
    int U = s_up[NGRP];
    for (int u = blockIdx.x; u < U; u += GRID3) {
        int g = 0;
        while (u >= s_up[g + 1]) g++;
        int ti = u - s_up[g];
        int s0 = g_gw[g][0] + ti * TILE;
        int cnt = min(TILE, g_gw[g][1] - s0);

        int tb = g * TPG + tid;
        float c[4][3];
        #pragma unroll
        for (int k = 0; k < 4; k++) {
            int t = tb + k * NT3;
            if (t < NTAR) {
                float4 q = g_t4[t];
                c[k][0] = -2.f * q.x; c[k][1] = -2.f * q.y; c[k][2] = -2.f * q.z;
            } else {
                c[k][0] = c[k][1] = c[k][2] = 0.f;
            }
        }
        unsigned long long txp0 = pk(c[0][0], c[1][0]), txp1 = pk(c[2][0], c[3][0]);
        unsigned long long typ0 = pk(c[0][1], c[1][1]), typ1 = pk(c[2][1], c[3][1]);
        unsigned long long tzp0 = pk(c[0][2], c[1][2]), tzp1 = pk(c[2][2], c[3][2]);

        __syncthreads();
        if (tid < 2 * cnt) s_tile[tid] = ((const float4*)g_s8)[2 * s0 + tid];
        __syncthreads();

        float m0 = FLT_BIG, m1 = FLT_BIG, m2 = FLT_BIG, m3 = FLT_BIG;
        const ulonglong2* st = (const ulonglong2*)s_tile;
        #pragma unroll 4
        for (int j = 0; j < cnt; j++) {
            ulonglong2 q = st[2 * j];
            ulonglong2 r = st[2 * j + 1];
            F2U v0 = fma2(q.x, txp0, r.y);
            F2U v1 = fma2(q.x, txp1, r.y);
            v0 = fma2(q.y, typ0, v0.u);
            v1 = fma2(q.y, typ1, v1.u);
            v0 = fma2(r.x, tzp0, v0.u);
            v1 = fma2(r.x, tzp1, v1.u);
            m0 = fminf(m0, v0.f.x);
            m1 = fminf(m1, v0.f.y);
            m2 = fminf(m2, v1.f.x);
            m3 = fminf(m3, v1.f.y);
        }
        if (tb < NTAR)           atomicMin(&g_pmk[tb],           fkey(m0));
        if (tb + NT3 < NTAR)     atomicMin(&g_pmk[tb + NT3],     fkey(m1));
        if (tb + 2 * NT3 < NTAR) atomicMin(&g_pmk[tb + 2 * NT3], fkey(m2));
        if (tb + 3 * NT3 < NTAR) atomicMin(&g_pmk[tb + 3 * NT3], fkey(m3));
    }
}

// ---- K4: margin -> bounded fallback (warp-skip) -> residual -> sum ----
__global__ __launch_bounds__(NT4) void finish_kernel(float* __restrict__ out) {
    __shared__ float4 s_tile[2 * TILEF];
    __shared__ float  s_fred[16];
    __shared__ int    s_up2[NGRP + 1];
    __shared__ int    s_last;
    int tid = threadIdx.x;
    int gid = blockIdx.x * NT4 + tid;

    // A: margin check vs original window -> per-group failure lists
    if (gid < NTAR) {
        int g = gid >> 10;                      // TPG == 1024
        float4 t = g_t4[gid];
        float d2 = fdec(g_pmk[gid]) + t.w;
        float mm = fminf(t.z - g_gz[g][0], g_gz[g][1] - t.z);
        if (!(d2 <= mm * mm)) {
            int slot = atomicAdd(&g_fcnt[g], 1);
            g_flistg[g * TPG + slot] = gid;
        }
    }
    gbar(NBLK4);

    // B: scan ONLY the +1-slab extension, per group, 4 targets/lane, warp-skip
    if (tid == 0) {
        int run = 0;
        #pragma unroll
        for (int g = 0; g < NGRP; g++) {
            int sz = (g_eL1[g] - g_eL0[g]) + (g_eR1[g] - g_eR0[g]);
            int t = (g_fcnt[g] > 0 && sz > 0) ? (sz + TILEF - 1) / TILEF : 0;
            s_up2[g] = run;
            run += t;
        }
        s_up2[NGRP] = run;
    }
    __syncthreads();
    int U2 = s_up2[NGRP];
    for (int u = blockIdx.x; u < U2; u += NBLK4) {
        int g = 0;
        while (u >= s_up2[g + 1]) g++;
        int ti = u - s_up2[g];
        int L0 = g_eL0[g], Lsz = g_eL1[g] - L0;
        int R0 = g_eR0[g], Rsz = g_eR1[g] - R0;
        int cbase = ti * TILEF;
        int cnt = min(TILEF, Lsz + Rsz - cbase);

        int fc = g_fcnt[g];
        int jj[4];
        float c[4][3];
        bool any = false;
        #pragma unroll
        for (int k = 0; k < 4; k++) {
            int fi = 4 * tid + k;
            jj[k] = (fi < fc) ? g_flistg[g * TPG + fi] : -1;
            if (jj[k] >= 0) {
                float4 t = g_t4[jj[k]];
                c[k][0] = -2.f * t.x; c[k][1] = -2.f * t.y; c[k][2] = -2.f * t.z;
                any = true;
            } else {
                c[k][0] = c[k][1] = c[k][2] = 0.f;
            }
        }

        __syncthreads();
        if (tid < 2 * cnt) {
            int e = cbase + (tid >> 1);
            int si = (e < Lsz) ? (L0 + e) : (R0 + e - Lsz);
            s_tile[tid] = ((const float4*)g_s8)[2 * si + (tid & 1)];
        }
        __syncthreads();

        // Warp-level skip: warps with no live targets don't run the loop.
        if (__ballot_sync(0xffffffffu, any)) {
            unsigned long long txp0 = pk(c[0][0], c[1][0]), txp1 = pk(c[2][0], c[3][0]);
            unsigned long long typ0 = pk(c[0][1], c[1][1]), typ1 = pk(c[2][1], c[3][1]);
            unsigned long long tzp0 = pk(c[0][2], c[1][2]), tzp1 = pk(c[2][2], c[3][2]);
            float m0 = FLT_BIG, m1 = FLT_BIG, m2 = FLT_BIG, m3 = FLT_BIG;
            const ulonglong2* st = (const ulonglong2*)s_tile;
            #pragma unroll 4
            for (int j = 0; j < cnt; j++) {
                ulonglong2 q = st[2 * j];
                ulonglong2 r = st[2 * j + 1];
                F2U v0 = fma2(q.x, txp0, r.y);
                F2U v1 = fma2(q.x, txp1, r.y);
                v0 = fma2(q.y, typ0, v0.u);
                v1 = fma2(q.y, typ1, v1.u);
                v0 = fma2(r.x, tzp0, v0.u);
                v1 = fma2(r.x, tzp1, v1.u);
                m0 = fminf(m0, v0.f.x);
                m1 = fminf(m1, v0.f.y);
                m2 = fminf(m2, v1.f.x);
                m3 = fminf(m3, v1.f.y);
            }
            if (jj[0] >= 0) atomicMin(&g_pmk[jj[0]], fkey(m0));
            if (jj[1] >= 0) atomicMin(&g_pmk[jj[1]], fkey(m1));
            if (jj[2] >= 0) atomicMin(&g_pmk[jj[2]], fkey(m2));
            if (jj[3] >= 0) atomicMin(&g_pmk[jj[3]], fkey(m3));
        }
    }
    gbar(NBLK4);

    // C: re-check vs EXTENDED edges; survivors -> flat residual list
    {
        int g = gid / TPG, idx = gid % TPG;
        if (g < NGRP && idx < g_fcnt[g]) {
            int j = g_flistg[g * TPG + idx];
            float4 t = g_t4[j];
            float d2 = fdec(g_pmk[j]) + t.w;
            float mm = fminf(t.z - g_em0[g], g_em1[g] - t.z);
            if (!(d2 <= mm * mm))
                g_flist[atomicAdd(&g_nfail, 1)] = j;
        }
    }
    gbar(NBLK4);

    // D: full brute force for residual targets, 4/lane, warp-skip
    int nf = g_nfail;
    if (nf > 0) {
        int nquad = (nf + 3) / 4;
        int fgroups = (nquad + NT4 - 1) / NT4;
        int UD = fgroups * NSTF;
        for (int u = blockIdx.x; u < UD; u += NBLK4) {
            int fg = u / NSTF, ti = u % NSTF;
            int base = 4 * (fg * NT4 + tid);
            int jj[4];
            float c[4][3];
            bool any = false;
            #pragma unroll
            for (int k = 0; k < 4; k++) {
                jj[k] = (base + k < nf) ? g_flist[base + k] : -1;
                if (jj[k] >= 0) {
                    float4 t = g_t4[jj[k]];
                    c[k][0] = -2.f * t.x; c[k][1] = -2.f * t.y; c[k][2] = -2.f * t.z;
                    any = true;
                } else {
                    c[k][0] = c[k][1] = c[k][2] = 0.f;
                }
            }

            int s0 = ti * TILEF;
            int cnt = min(TILEF, NSRC - s0);
            __syncthreads();
            if (tid < 2 * cnt) s_tile[tid] = ((const float4*)g_s8)[2 * s0 + tid];
            __syncthreads();

            if (__ballot_sync(0xffffffffu, any)) {
                unsigned long long txp0 = pk(c[0][0], c[1][0]), txp1 = pk(c[2][0], c[3][0]);
                unsigned long long typ0 = pk(c[0][1], c[1][1]), typ1 = pk(c[2][1], c[3][1]);
                unsigned long long tzp0 = pk(c[0][2], c[1][2]), tzp1 = pk(c[2][2], c[3][2]);
                float m0 = FLT_BIG, m1 = FLT_BIG, m2 = FLT_BIG, m3 = FLT_BIG;
                const ulonglong2* st = (const ulonglong2*)s_tile;
                #pragma unroll 4
                for (int j = 0; j < cnt; j++) {
                    ulonglong2 q = st[2 * j];
                    ulonglong2 r = st[2 * j + 1];
                    F2U v0 = fma2(q.x, txp0, r.y);
                    F2U v1 = fma2(q.x, txp1, r.y);
                    v0 = fma2(q.y, typ0, v0.u);
                    v1 = fma2(q.y, typ1, v1.u);
                    v0 = fma2(r.x, tzp0, v0.u);
                    v1 = fma2(r.x, tzp1, v1.u);
                    m0 = fminf(m0, v0.f.x);
                    m1 = fminf(m1, v0.f.y);
                    m2 = fminf(m2, v1.f.x);
                    m3 = fminf(m3, v1.f.y);
                }
                if (jj[0] >= 0) atomicMin(&g_pmk[jj[0]], fkey(m0));
                if (jj[1] >= 0) atomicMin(&g_pmk[jj[1]], fkey(m1));
                if (jj[2] >= 0) atomicMin(&g_pmk[jj[2]], fkey(m2));
                if (jj[3] >= 0) atomicMin(&g_pmk[jj[3]], fkey(m3));
            }
        }
    }

    // Ticket: last block does the fixed-order final sum
    __threadfence();
    __syncthreads();
    if (tid == 0) {
        unsigned t = atomicAdd(&g_tick4, 1u);
        s_last = (t == NBLK4 - 1) ? 1 : 0;
        if (s_last) g_tick4 = 0;
    }
    __syncthreads();
    if (!s_last) return;
    __threadfence();

    float acc = 0.f;
    for (int j = tid; j < NTAR; j += NT4)
        acc += fdec(g_pmk[j]) + g_t4[j].w;
    int lane = tid & 31, wid = tid >> 5;
    #pragma unroll
    for (int o = 16; o; o >>= 1) acc += __shfl_down_sync(0xffffffffu, acc, o);
    if (lane == 0) s_fred[wid] = acc;
    __syncthreads();
    if (wid == 0) {
        float v = (lane < 16) ? s_fred[lane] : 0.f;
        #pragma unroll
        for (int o = 8; o; o >>= 1) v += __shfl_down_sync(0xffffffffu, v, o);
        if (lane == 0) out[0] = 0.5f * v;
    }
}

extern "C" void kernel_launch(void* const* d_in, const int* in_sizes, int n_in,
                              void* d_out, int out_size) {
    const float* src = (const float*)d_in[0];   // [20000, 3] fp32
    const float* tar = (const float*)d_in[1];   // [20000, 3] fp32
    float* out = (float*)d_out;                 // scalar fp32

    hist_setup_kernel<<<NB1, NT1>>>(src, tar);
    scatter_kernel<<<NB1, NT1>>>(src, tar);
    pair_kernel<<<GRID3, NT3>>>();
    finish_kernel<<<NBLK4, NT4>>>(out);
}

// round 17
// speedup vs baseline: 1.6073x; 1.4036x over previous
#include <cuda_runtime.h>

#define NSRC 20000
#define NTAR 20000
#define NTOT (NSRC + NTAR)
#define NBIN 2048
#define ZMINV (-4.0f)
#define BINW (8.0f / NBIN)
#define INVBINW (NBIN / 8.0f)
#define NS   16
#define SLABQ (NSRC / NS)                  // 1250
#define NB1  40
#define NT1  1024
#define GRID3 296
#define NT3  256
#define TILE 128
#define TPG  1024                          // targets per group
#define NGRP 20
#define NBLK4 148
#define NT4  512
#define TILEF 256
#define NSTF ((NSRC + TILEF - 1) / TILEF)  // 79
#define FLT_BIG 3.402823466e38f
#define INF_KEY 0x7F800000

// ---- device-global scratch (no allocation allowed) ----
__device__ int    g_histS[NBIN];
__device__ int    g_histT[NBIN];
__device__ int    g_lut[NBIN];
__device__ int    g_fill[2 * NS];
__device__ float  g_s8[NSRC * 8];         // slab-sorted packed {x,x,y,y,z,z,w,w}
__device__ float4 g_t4[NTAR];             // slab-sorted targets {x,y,z,||t||^2}
__device__ int    g_pmk[NTAR];            // per-sorted-target min key
__device__ int    g_gw[NGRP][2];          // window src range
__device__ float  g_gz[NGRP][2];          // window z-edges
__device__ int    g_upref[NGRP + 1];
__device__ int    g_nfail;
__device__ int    g_flist[NTAR];
__device__ unsigned g_tick1, g_tick4;     // last-block tickets (self-resetting)
__device__ unsigned          g_bar_cnt;
__device__ volatile unsigned g_bar_gen;   // monotonic

union F2U { unsigned long long u; float2 f; };
__device__ __forceinline__ unsigned long long pk(float lo, float hi) {
    F2U t; t.f = make_float2(lo, hi); return t.u;
}
__device__ __forceinline__ F2U fma2(unsigned long long a, unsigned long long b,
                                    unsigned long long c) {
    F2U d;
    asm("fma.rn.f32x2 %0, %1, %2, %3;" : "=l"(d.u) : "l"(a), "l"(b), "l"(c));
    return d;
}
__device__ __forceinline__ int fkey(float f) {
    int b = __float_as_int(f);
    return b >= 0 ? b : (b ^ 0x7FFFFFFF);
}
__device__ __forceinline__ float fdec(int k) {
    return __int_as_float(k >= 0 ? k : (k ^ 0x7FFFFFFF));
}
__device__ __forceinline__ int finebin(float z) {
    int b = (int)floorf((z - ZMINV) * INVBINW);
    return min(max(b, 0), NBIN - 1);
}

// inclusive scan of 2048 bins with 1024 threads (2 bins each)
__device__ void scan2048_1024(const int* hist, int* s_cum, int* s_ws) {
    int tid = threadIdx.x;
    int base = tid * 2;
    int2 q = *(const int2*)&hist[base];
    int tot = q.x + q.y;
    int lane = tid & 31, wid = tid >> 5;
    int inc = tot;
    #pragma unroll
    for (int o = 1; o < 32; o <<= 1) {
        int y = __shfl_up_sync(0xffffffffu, inc, o);
        if (lane >= o) inc += y;
    }
    if (lane == 31) s_ws[wid] = inc;
    __syncthreads();
    if (wid == 0) {
        int w = s_ws[lane];
        #pragma unroll
        for (int o = 1; o < 32; o <<= 1) {
            int y = __shfl_up_sync(0xffffffffu, w, o);
            if (lane >= o) w += y;
        }
        s_ws[lane] = w;
    }
    __syncthreads();
    int run = inc - tot + (wid ? s_ws[wid - 1] : 0);
    run += q.x; s_cum[base]     = run;
    run += q.y; s_cum[base + 1] = run;
    __syncthreads();
}

// ---- K1: reset + histograms; last (ticketed) block does all setup ----
__global__ __launch_bounds__(NT1) void hist_setup_kernel(const float* __restrict__ src,
                                                         const float* __restrict__ tar) {
    __shared__ int   s_cum[NBIN];
    __shared__ int   s_ws[32];
    __shared__ int   s_bnd[NS + 1];
    __shared__ int   s_soff[NS + 1];
    __shared__ int   s_toff[NS + 1];
    __shared__ float s_edge[NS + 1];
    __shared__ int   s_last;
    int tid = threadIdx.x;
    int i = blockIdx.x * NT1 + tid;

    if (i == 0) g_nfail = 0;
    if (i < NTAR) g_pmk[i] = INF_KEY;
    if (i < NTOT) {
        if (i < NSRC) atomicAdd(&g_histS[finebin(src[3 * i + 2])], 1);
        else          atomicAdd(&g_histT[finebin(tar[3 * (i - NSRC) + 2])], 1);
    }
    __threadfence();
    __syncthreads();
    if (tid == 0) {
        unsigned t = atomicAdd(&g_tick1, 1u);
        s_last = (t == NB1 - 1) ? 1 : 0;
        if (s_last) g_tick1 = 0;          // reset for next replay
    }
    __syncthreads();
    if (!s_last) return;
    __threadfence();

    // --- setup (one block) ---
    scan2048_1024(g_histS, s_cum, s_ws);
    if (tid >= 1 && tid < NS) {
        int tgt = tid * SLABQ;
        int lo = 0, hi = NBIN - 1;
        while (lo < hi) { int mid = (lo + hi) >> 1; if (s_cum[mid] >= tgt) hi = mid; else lo = mid + 1; }
        s_bnd[tid] = lo + 1;
    }
    if (tid == 0) { s_bnd[0] = 0; s_bnd[NS] = NBIN; }
    __syncthreads();
    if (tid <= NS) {
        s_soff[tid] = (tid == 0) ? 0 : s_cum[s_bnd[tid] - 1];
        s_edge[tid] = (tid == 0) ? -1e30f :
                      (tid == NS) ? 1e30f : (ZMINV + (float)s_bnd[tid] * BINW);
    }
    __syncthreads();
    for (int b = tid; b < NBIN; b += NT1) {
        int s = 0;
        #pragma unroll
        for (int k = 1; k < NS; k++) s += (s_bnd[k] <= b) ? 1 : 0;
        g_lut[b] = s;
        g_histS[b] = 0;                   // reset for next replay
    }
    __syncthreads();
    scan2048_1024(g_histT, s_cum, s_ws);
    if (tid <= NS) s_toff[tid] = (tid == 0) ? 0 : s_cum[s_bnd[tid] - 1];
    for (int b = tid; b < NBIN; b += NT1) g_histT[b] = 0;
    __syncthreads();
    if (tid < NS) {
        g_fill[tid]      = s_soff[tid];
        g_fill[NS + tid] = s_toff[tid];
    }
    if (tid < NGRP) {                     // windows from target ranks
        int j0 = tid * TPG;
        int j1 = min(j0 + TPG, NTAR) - 1;
        int sf = 0, sl = 0;
        #pragma unroll
        for (int k = 1; k < NS; k++) {
            sf += (s_toff[k] <= j0) ? 1 : 0;
            sl += (s_toff[k] <= j1) ? 1 : 0;
        }
        int lo = max(sf - 1, 0), hi = min(sl + 1, NS - 1);
        g_gw[tid][0] = s_soff[lo];
        g_gw[tid][1] = s_soff[hi + 1];
        g_gz[tid][0] = s_edge[lo];
        g_gz[tid][1] = s_edge[hi + 1];
    }
    __syncthreads();
    if (tid == 0) {
        int run = 0;
        for (int g = 0; g < NGRP; g++) {
            g_upref[g] = run;
            run += (g_gw[g][1] - g_gw[g][0] + TILE - 1) / TILE;
        }
        g_upref[NGRP] = run;
    }
}

// ---- K2: block-aggregated counting-sort scatter ----
__global__ __launch_bounds__(NT1) void scatter_kernel(const float* __restrict__ src,
                                                      const float* __restrict__ tar) {
    __shared__ int s_hcnt[2 * NS];
    __shared__ int s_hbase[2 * NS];
    int tid = threadIdx.x;
    int i = blockIdx.x * NT1 + tid;
    bool valid = (i < NTOT);
    int slab = 0;
    float x = 0.f, y = 0.f, z = 0.f;
    if (valid) {
        if (i < NSRC) {
            x = src[3 * i]; y = src[3 * i + 1]; z = src[3 * i + 2];
            slab = g_lut[finebin(z)];
        } else {
            int t = i - NSRC;
            x = tar[3 * t]; y = tar[3 * t + 1]; z = tar[3 * t + 2];
            slab = NS + g_lut[finebin(z)];
        }
    }
    if (tid < 2 * NS) s_hcnt[tid] = 0;
    __syncthreads();
    int lpos = 0;
    if (valid) lpos = atomicAdd(&s_hcnt[slab], 1);
    __syncthreads();
    if (tid < 2 * NS && s_hcnt[tid] > 0)
        s_hbase[tid] = atomicAdd(&g_fill[tid], s_hcnt[tid]);
    __syncthreads();
    if (valid) {
        int pos = s_hbase[slab] + lpos;
        float w = x * x + y * y + z * z;
        if (i < NSRC) {
            float4* p = (float4*)g_s8;
            p[2 * pos]     = make_float4(x, x, y, y);
            p[2 * pos + 1] = make_float4(z, z, w, w);
        } else {
            g_t4[pos] = make_float4(x, y, z, w);
        }
    }
}

// ---- K3: windowed pairwise min, 4 targets/lane ----
__global__ __launch_bounds__(NT3) void pair_kernel() {
    __shared__ float4 s_tile[2 * TILE];
    __shared__ int    s_up[NGRP + 1];
    int tid = threadIdx.x;
    if (tid <= NGRP) s_up[tid] = g_upref[tid];
    __syncthreads();
    int U = s_up[NGRP];
    for (int u = blockIdx.x; u < U; u += GRID3) {
        int g = 0;
        while (u >= s_up[g + 1]) g++;
        int ti = u - s_up[g];
        int s0 = g_gw[g][0] + ti * TILE;
        int cnt = min(TILE, g_gw[g][1] - s0);

        int tb = g * TPG + tid;
        float c[4][3];
        #pragma unroll
        for (int k = 0; k < 4; k++) {
            int t = tb + k * NT3;
            if (t < NTAR) {
                float4 q = g_t4[t];
                c[k][0] = -2.f * q.x; c[k][1] = -2.f * q.y; c[k][2] = -2.f * q.z;
            } else {
                c[k][0] = c[k][1] = c[k][2] = 0.f;
            }
        }
        unsigned long long txp0 = pk(c[0][0], c[1][0]), txp1 = pk(c[2][0], c[3][0]);
        unsigned long long typ0 = pk(c[0][1], c[1][1]), typ1 = pk(c[2][1], c[3][1]);
        unsigned long long tzp0 = pk(c[0][2], c[1][2]), tzp1 = pk(c[2][2], c[3][2]);

        __syncthreads();
        if (tid < 2 * cnt) s_tile[tid] = ((const float4*)g_s8)[2 * s0 + tid];
        __syncthreads();

        float m0 = FLT_BIG, m1 = FLT_BIG, m2 = FLT_BIG, m3 = FLT_BIG;
        const ulonglong2* st = (const ulonglong2*)s_tile;
        #pragma unroll 4
        for (int j = 0; j < cnt; j++) {
            ulonglong2 q = st[2 * j];
            ulonglong2 r = st[2 * j + 1];
            F2U v0 = fma2(q.x, txp0, r.y);
            F2U v1 = fma2(q.x, txp1, r.y);
            v0 = fma2(q.y, typ0, v0.u);
            v1 = fma2(q.y, typ1, v1.u);
            v0 = fma2(r.x, tzp0, v0.u);
            v1 = fma2(r.x, tzp1, v1.u);
            m0 = fminf(m0, v0.f.x);
            m1 = fminf(m1, v0.f.y);
            m2 = fminf(m2, v1.f.x);
            m3 = fminf(m3, v1.f.y);
        }
        if (tb < NTAR)           atomicMin(&g_pmk[tb],           fkey(m0));
        if (tb + NT3 < NTAR)     atomicMin(&g_pmk[tb + NT3],     fkey(m1));
        if (tb + 2 * NT3 < NTAR) atomicMin(&g_pmk[tb + 2 * NT3], fkey(m2));
        if (tb + 3 * NT3 < NTAR) atomicMin(&g_pmk[tb + 3 * NT3], fkey(m3));
    }
}

// ---- K4: margin + full-brute fallback (warp-skip) + final sum ----
// One hot-spin grid barrier + one ticket. (R11 structure.)
__global__ __launch_bounds__(NT4) void finish_kernel(float* __restrict__ out) {
    __shared__ float4 s_tile[2 * TILEF];
    __shared__ float  s_fred[16];
    __shared__ int    s_last;
    int tid = threadIdx.x;
    int gid = blockIdx.x * NT4 + tid;

    // Phase A: margin check -> failure list
    if (gid < NTAR) {
        int g = gid >> 10;                      // TPG == 1024
        float4 t = g_t4[gid];
        float d2 = fdec(g_pmk[gid]) + t.w;
        float mm = fminf(t.z - g_gz[g][0], g_gz[g][1] - t.z);
        if (!(d2 <= mm * mm))
            g_flist[atomicAdd(&g_nfail, 1)] = gid;
    }

    // One grid barrier — hot spin (no nanosleep), 148 resident blocks
    __threadfence();
    __syncthreads();
    if (tid == 0) {
        unsigned gen = g_bar_gen;
        if (atomicAdd(&g_bar_cnt, 1u) == NBLK4 - 1) {
            g_bar_cnt = 0;
            __threadfence();
            g_bar_gen = gen + 1;
        } else {
            while (g_bar_gen == gen) { }        // hot spin on one L2 line
            __threadfence();
        }
    }
    __syncthreads();

    // Phase B: full brute force over all srcs, 4 failed targets/lane, warp-skip
    int nf = g_nfail;
    {
        int nquad = (nf + 3) / 4;
        int fgroups = (nquad + NT4 - 1) / NT4;
        int U2 = fgroups * NSTF;
        for (int u = blockIdx.x; u < U2; u += NBLK4) {
            int fg = u / NSTF, ti = u % NSTF;
            int base = 4 * (fg * NT4 + tid);
            int jj[4];
            float c[4][3];
            bool any = false;
            #pragma unroll
            for (int k = 0; k < 4; k++) {
                jj[k] = (base + k < nf) ? g_flist[base + k] : -1;
                if (jj[k] >= 0) {
                    float4 t = g_t4[jj[k]];
                    c[k][0] = -2.f * t.x; c[k][1] = -2.f * t.y; c[k][2] = -2.f * t.z;
                    any = true;
                } else {
                    c[k][0] = c[k][1] = c[k][2] = 0.f;
                }
            }

            int s0 = ti * TILEF;
            int cnt = min(TILEF, NSRC - s0);
            __syncthreads();
            if (tid < 2 * cnt) s_tile[tid] = ((const float4*)g_s8)[2 * s0 + tid];
            __syncthreads();

            if (__ballot_sync(0xffffffffu, any)) {    // warp-level skip
                unsigned long long txp0 = pk(c[0][0], c[1][0]), txp1 = pk(c[2][0], c[3][0]);
                unsigned long long typ0 = pk(c[0][1], c[1][1]), typ1 = pk(c[2][1], c[3][1]);
                unsigned long long tzp0 = pk(c[0][2], c[1][2]), tzp1 = pk(c[2][2], c[3][2]);
                float m0 = FLT_BIG, m1 = FLT_BIG, m2 = FLT_BIG, m3 = FLT_BIG;
                const ulonglong2* st = (const ulonglong2*)s_tile;
                #pragma unroll 4
                for (int j = 0; j < cnt; j++) {
                    ulonglong2 q = st[2 * j];
                    ulonglong2 r = st[2 * j + 1];
                    F2U v0 = fma2(q.x, txp0, r.y);
                    F2U v1 = fma2(q.x, txp1, r.y);
                    v0 = fma2(q.y, typ0, v0.u);
                    v1 = fma2(q.y, typ1, v1.u);
                    v0 = fma2(r.x, tzp0, v0.u);
                    v1 = fma2(r.x, tzp1, v1.u);
                    m0 = fminf(m0, v0.f.x);
                    m1 = fminf(m1, v0.f.y);
                    m2 = fminf(m2, v1.f.x);
                    m3 = fminf(m3, v1.f.y);
                }
                if (jj[0] >= 0) atomicMin(&g_pmk[jj[0]], fkey(m0));
                if (jj[1] >= 0) atomicMin(&g_pmk[jj[1]], fkey(m1));
                if (jj[2] >= 0) atomicMin(&g_pmk[jj[2]], fkey(m2));
                if (jj[3] >= 0) atomicMin(&g_pmk[jj[3]], fkey(m3));
            }
        }
    }

    // Ticket: last block does the fixed-order final sum (deterministic)
    __threadfence();
    __syncthreads();
    if (tid == 0) {
        unsigned t = atomicAdd(&g_tick4, 1u);
        s_last = (t == NBLK4 - 1) ? 1 : 0;
        if (s_last) g_tick4 = 0;          // reset for next replay
    }
    __syncthreads();
    if (!s_last) return;
    __threadfence();

    float acc = 0.f;
    for (int j = tid; j < NTAR; j += NT4)        // fixed per-thread order
        acc += fdec(g_pmk[j]) + g_t4[j].w;
    int lane = tid & 31, wid = tid >> 5;
    #pragma unroll
    for (int o = 16; o; o >>= 1) acc += __shfl_down_sync(0xffffffffu, acc, o);
    if (lane == 0) s_fred[wid] = acc;
    __syncthreads();
    if (wid == 0) {
        float v = (lane < 16) ? s_fred[lane] : 0.f;
        #pragma unroll
        for (int o = 8; o; o >>= 1) v += __shfl_down_sync(0xffffffffu, v, o);
        if (lane == 0) out[0] = 0.5f * v;
    }
}

extern "C" void kernel_launch(void* const* d_in, const int* in_sizes, int n_in,
                              void* d_out, int out_size) {
    const float* src = (const float*)d_in[0];   // [20000, 3] fp32
    const float* tar = (const float*)d_in[1];   // [20000, 3] fp32
    float* out = (float*)d_out;                 // scalar fp32

    hist_setup_kernel<<<NB1, NT1>>>(src, tar);
    scatter_kernel<<<NB1, NT1>>>(src, tar);
    pair_kernel<<<GRID3, NT3>>>();
    finish_kernel<<<NBLK4, NT4>>>(out);
}